// round 7
// baseline (speedup 1.0000x reference)
#include <cuda_runtime.h>

typedef unsigned long long ull;
typedef long long ll;

#define HDIM 64
#define GDIM 192  // 3*HDIM
#define MAXT 256
#define MAXB 16384
#define MAXV 102400
#define NTHR 128
#define ROWS 8  // rows per CTA (4 per thread for gates)

// ---------------- device globals (no allocation allowed) ----------------
__device__ int g_tok64;
__device__ int g_pos64;
__device__ int g_hist[256];
__device__ int g_order[MAXB];
__device__ float g_proj[(size_t)MAXV * GDIM];  // emb @ W_ih^T, ~78.6MB

// ---------------- helpers ----------------
__device__ __forceinline__ ull ffma2(ull a, ull b, ull c) {
  ull d;
  asm("fma.rn.f32x2 %0, %1, %2, %3;" : "=l"(d) : "l"(a), "l"(b), "l"(c));
  return d;
}
__device__ __forceinline__ float pair_sum(ull a) {
  unsigned lo, hi;
  asm("mov.b64 {%0, %1}, %2;" : "=r"(lo), "=r"(hi) : "l"(a));
  return __uint_as_float(lo) + __uint_as_float(hi);
}
__device__ __forceinline__ float rcp_fast(float x) {
  float y;
  asm("rcp.approx.f32 %0, %1;" : "=f"(y) : "f"(x));
  return y;
}
__device__ __forceinline__ float sigm(float x) {
  return rcp_fast(1.0f + __expf(-x));
}
__device__ __forceinline__ float tanh_f(float x) {
  return 1.0f - 2.0f * rcp_fast(__expf(2.0f * x) + 1.0f);
}
__device__ __forceinline__ int load_len_(const void* sp, int b, int T, int p64) {
  int v = p64 ? (int)((const ll*)sp)[b] : ((const int*)sp)[b];
  return min(max(v, 1), T);
}
__device__ __forceinline__ int load_tok_(const void* st, ll idx, int t64) {
  return t64 ? (int)((const ll*)st)[idx] : ((const int*)st)[idx];
}

// ---------------- preamble 1: dtype detect + length histogram (1 CTA) -------
__global__ void k_prep(const int* tok, const int* pos, int B, int T) {
  __shared__ int h_sm[256];
  int i = threadIdx.x;
  if (i == 0) {
    int t64 = 1, p64 = 1;
#pragma unroll
    for (int k = 1; k < 32; k += 2) {
      if (tok[k] != 0) t64 = 0;
      if (pos[k] != 0) p64 = 0;
    }
    g_tok64 = t64;
    g_pos64 = p64;
  }
  h_sm[i] = 0;
  __syncthreads();
  int p64 = g_pos64;
  for (int b = i; b < B; b += 256) {
    int v = p64 ? (int)((const ll*)pos)[b] : pos[b];
    int len = min(max(v, 1), T);
    atomicAdd(&h_sm[min(T - len, 255)], 1);  // bin 0 = longest
  }
  __syncthreads();
  g_hist[i] = h_sm[i];
}

// ---------------- preamble 2: scan + scatter (1 CTA) ----------------
__global__ void k_scanscatter(const void* pos, int B, int T) {
  __shared__ int v[256];
  __shared__ int cur[256];
  int i = threadIdx.x;
  int x = g_hist[i];
  v[i] = x;
  __syncthreads();
#pragma unroll
  for (int off = 1; off < 256; off <<= 1) {
    int t = (i >= off) ? v[i - off] : 0;
    __syncthreads();
    v[i] += t;
    __syncthreads();
  }
  cur[i] = v[i] - x;
  __syncthreads();
  int p64 = g_pos64;
  for (int b = i; b < B; b += 256) {
    int len = load_len_(pos, b, T, p64);
    int bin = min(T - len, 255);
    int p = atomicAdd(&cur[bin], 1);
    if (p < MAXB) g_order[p] = b;
  }
}

// ---------------- vocab projection: g_proj = emb @ W_ih^T ----------------
#define PROJ_RPI 16
__global__ void __launch_bounds__(GDIM, 3) k_proj(const float* __restrict__ emb,
                                                  const float* __restrict__ W_ih,
                                                  int V) {
  __shared__ __align__(16) float e_sm[2][PROJ_RPI][HDIM];
  const int j = threadIdx.x;

  ull w[32];
  {
    const ulonglong2* wr = (const ulonglong2*)(W_ih + j * HDIM);
#pragma unroll
    for (int k = 0; k < 16; k++) {
      ulonglong2 a = wr[k];
      w[2 * k] = a.x;
      w[2 * k + 1] = a.y;
    }
  }

  int per = (V + gridDim.x - 1) / gridDim.x;
  per = (per + PROJ_RPI - 1) & ~(PROJ_RPI - 1);
  const int vbeg = blockIdx.x * per;
  const int vend = min(vbeg + per, V);
  if (vbeg >= vend) return;

  // stage first 16 rows into buf 0 (256 float4 by 192 threads)
  for (int i = j; i < PROJ_RPI * 16; i += GDIM) {
    int row = i >> 4, lane = i & 15;
    int v = vbeg + row;
    if (v < vend)
      ((float4*)e_sm[0][row])[lane] = ((const float4*)(emb + (ll)v * HDIM))[lane];
  }
  __syncthreads();

  int buf = 0;
  for (int v = vbeg; v < vend; v += PROJ_RPI) {
    for (int i = j; i < PROJ_RPI * 16; i += GDIM) {
      int row = i >> 4, lane = i & 15;
      int vn = v + PROJ_RPI + row;
      if (vn < vend)
        ((float4*)e_sm[buf ^ 1][row])[lane] =
            ((const float4*)(emb + (ll)vn * HDIM))[lane];
    }
    ull acc[PROJ_RPI];
#pragma unroll
    for (int i = 0; i < PROJ_RPI; i++) acc[i] = 0ull;
#pragma unroll
    for (int k = 0; k < 16; k++) {
#pragma unroll
      for (int i = 0; i < PROJ_RPI; i++) {
        ulonglong2 q = ((const ulonglong2*)e_sm[buf][i])[k];
        acc[i] = ffma2(w[2 * k], q.x, acc[i]);
        acc[i] = ffma2(w[2 * k + 1], q.y, acc[i]);
      }
    }
#pragma unroll
    for (int i = 0; i < PROJ_RPI; i++)
      if (v + i < vend) g_proj[(ll)(v + i) * GDIM + j] = pair_sum(acc[i]);
    __syncthreads();
    buf ^= 1;
  }
}

// ---------------- fused GRU recurrence (k-split, L1-streamed W) ----------
// CTA = 128 threads: kh = (tid>>4)&1 (k-half), j = (tid&15)|((tid>>5)<<4)
// (unit 0..63). 8 rows per CTA. Each thread: partial dots (its 32 k's) for
// all 8 rows x 3 gates, W_hh half-rows STREAMED from L1 each step (no reg
// residency -> 3 CTAs/SM, 24 rows/SM); shfl.xor(16) combines halves; gates +
// h-update for own 4 rows (kh=0 -> rows 0-3, kh=1 -> 4-7). One barrier/step.
__global__ void __launch_bounds__(NTHR, 3) k_gru(
    const void* __restrict__ seq_token, const void* __restrict__ seq_pos,
    const float* __restrict__ W_hh, float* __restrict__ out, int B, int T) {
  __shared__ int tok_sm[ROWS][MAXT];
  __shared__ __align__(16) float h_sm[2][ROWS][2][36];  // [buf][row][khalf][32+pad]
  __shared__ int s_row[ROWS], s_len[ROWS];

  const int tid = threadIdx.x;
  const int kh = (tid >> 4) & 1;
  const int j = (tid & 15) | ((tid >> 5) << 4);
  const int rbase = kh * 4;  // own rows: rbase..rbase+3
  const int tok64 = g_tok64;

  // snake CTA->rank permutation: pairs long blocks with short blocks on the
  // same SM (classic placement maps bid and bid+148 to one SM).
  int rank;
  {
    const int nblk = gridDim.x;
    const int bid = blockIdx.x;
    const int q = bid % 296;
    const int base = bid - q;
    rank = (base + 296 <= nblk) ? (base + ((q < 148) ? q : 443 - q)) : bid;
  }

  if (tid < ROWS) {
    int idx = ROWS * rank + tid;
    int row = (idx < B) ? g_order[idx] : -1;
    s_row[tid] = row;
    s_len[tid] = (row >= 0) ? load_len_(seq_pos, row, T, g_pos64) : 0;
  }
  __syncthreads();
  int tmax = 0;
  int lens[4];
#pragma unroll
  for (int r = 0; r < ROWS; r++) tmax = max(tmax, s_len[r]);
  if (tmax > MAXT) tmax = MAXT;
#pragma unroll
  for (int r = 0; r < 4; r++) lens[r] = s_len[rbase + r];

  // stage token ids (as int32) into smem
#pragma unroll
  for (int r = 0; r < ROWS; r++) {
    int rw = s_row[r];
    for (int i = tid; i < tmax; i += NTHR)
      tok_sm[r][i] = (rw >= 0) ? load_tok_(seq_token, (ll)rw * T + i, tok64) : 0;
  }

  // W_hh half-row pointers for unit j, 3 gates (streamed from L1 per step)
  const ulonglong2* __restrict__ wrp =
      (const ulonglong2*)(W_hh + j * HDIM + kh * 32);
  const ulonglong2* __restrict__ wzp =
      (const ulonglong2*)(W_hh + (HDIM + j) * HDIM + kh * 32);
  const ulonglong2* __restrict__ wnp =
      (const ulonglong2*)(W_hh + (2 * HDIM + j) * HDIM + kh * 32);

  // init h = 0 in buffer 0 (own-row slots)
#pragma unroll
  for (int r = 0; r < 4; r++) h_sm[0][rbase + r][j >> 5][j & 31] = 0.0f;
  __syncthreads();  // tok_sm + h ready

  for (int t = 0; t < tmax; t++) {
    const int cur = t & 1, nxt = cur ^ 1;

    // gi gathers for own 4 rows (evict-first: protect L1 for W); consumed
    // only after ~2000 cyc of dots -> latency fully hidden.
    float gr[4], gz[4], gn[4];
#pragma unroll
    for (int r = 0; r < 4; r++) {
      const float* p = g_proj + (ll)tok_sm[rbase + r][t] * GDIM + j;
      gr[r] = __ldcs(p);
      gz[r] = __ldcs(p + 64);
      gn[r] = __ldcs(p + 128);
    }

    // partial dots over this thread's k-half, all 8 rows x 3 gates
    ull acc[ROWS][3];
#pragma unroll
    for (int r = 0; r < ROWS; r++) {
      acc[r][0] = 0ull;
      acc[r][1] = 0ull;
      acc[r][2] = 0ull;
    }
#pragma unroll
    for (int k = 0; k < 8; k++) {
      ulonglong2 wr = wrp[k];
      ulonglong2 wz = wzp[k];
      ulonglong2 wn = wnp[k];
#pragma unroll
      for (int r = 0; r < ROWS; r++) {
        ulonglong2 hq = ((const ulonglong2*)h_sm[cur][r][kh])[k];
        acc[r][0] = ffma2(wr.x, hq.x, acc[r][0]);
        acc[r][0] = ffma2(wr.y, hq.y, acc[r][0]);
        acc[r][1] = ffma2(wz.x, hq.x, acc[r][1]);
        acc[r][1] = ffma2(wz.y, hq.y, acc[r][1]);
        acc[r][2] = ffma2(wn.x, hq.x, acc[r][2]);
        acc[r][2] = ffma2(wn.y, hq.y, acc[r][2]);
      }
    }

    // combine halves with partner lane (lane ^ 16, same j, other kh)
    float f[ROWS][3];
#pragma unroll
    for (int r = 0; r < ROWS; r++) {
#pragma unroll
      for (int gg = 0; gg < 3; gg++) {
        float p = pair_sum(acc[r][gg]);
        f[r][gg] = p + __shfl_xor_sync(0xffffffffu, p, 16);
      }
    }

    // gates + h update for own 4 rows, fully in-thread
#pragma unroll
    for (int r = 0; r < 4; r++) {
      const int rr = rbase + r;
      float sr = sigm(gr[r] + f[rr][0]);
      float sz = sigm(gz[r] + f[rr][1]);
      float nn = tanh_f(gn[r] + sr * f[rr][2]);
      float ho = h_sm[cur][rr][j >> 5][j & 31];
      float hn = (1.0f - sz) * nn + sz * ho;
      h_sm[nxt][rr][j >> 5][j & 31] = (t < lens[r]) ? hn : ho;
    }
    __syncthreads();  // h[nxt] complete; fences reads of h[cur]
  }

  const int fb = tmax & 1;  // final h buffer
#pragma unroll
  for (int r = 0; r < 4; r++) {
    int row = s_row[rbase + r];
    if (row >= 0) out[(ll)row * HDIM + j] = h_sm[fb][rbase + r][j >> 5][j & 31];
  }
}

// ---------------- launch ----------------
extern "C" void kernel_launch(void* const* d_in, const int* in_sizes, int n_in,
                              void* d_out, int out_size) {
  const void* tok = d_in[0];
  const void* pos = d_in[1];
  const float* emb = (const float*)d_in[2];
  const float* wih = (const float*)d_in[3];
  const float* whh = (const float*)d_in[4];
  float* out = (float*)d_out;

  const int B = in_sizes[1];
  const int T = in_sizes[0] / (B > 0 ? B : 1);
  int V = in_sizes[2] / HDIM;
  if (V > MAXV) V = MAXV;

  k_prep<<<1, 256>>>((const int*)tok, (const int*)pos, B, T);
  k_scanscatter<<<1, 256>>>(pos, B, T);
  k_proj<<<1184, GDIM>>>(emb, wih, V);

  const int nblk = (B + ROWS - 1) / ROWS;
  k_gru<<<nblk, NTHR>>>(tok, pos, whh, out, B, T);
}

// round 8
// speedup vs baseline: 2.7947x; 2.7947x over previous
#include <cuda_runtime.h>

typedef unsigned long long ull;
typedef long long ll;

#define HDIM 64
#define GDIM 192  // 3*HDIM
#define MAXT 256
#define MAXB 16384
#define MAXV 102400
#define NTHR 128  // (k-half) x (64 units) -> lane = kh*16 pattern
#define ROWS 4    // rows per CTA

// ---------------- device globals (no allocation allowed) ----------------
__device__ int g_tok64;
__device__ int g_pos64;
__device__ int g_hist[256];
__device__ int g_order[MAXB];
__device__ float g_proj[(size_t)MAXV * GDIM];  // emb @ W_ih^T, ~78.6MB

// ---------------- helpers ----------------
__device__ __forceinline__ ull ffma2(ull a, ull b, ull c) {
  ull d;
  asm("fma.rn.f32x2 %0, %1, %2, %3;" : "=l"(d) : "l"(a), "l"(b), "l"(c));
  return d;
}
__device__ __forceinline__ float pair_sum(ull a) {
  unsigned lo, hi;
  asm("mov.b64 {%0, %1}, %2;" : "=r"(lo), "=r"(hi) : "l"(a));
  return __uint_as_float(lo) + __uint_as_float(hi);
}
__device__ __forceinline__ float rcp_fast(float x) {
  float y;
  asm("rcp.approx.f32 %0, %1;" : "=f"(y) : "f"(x));
  return y;
}
__device__ __forceinline__ float sigm(float x) {
  return rcp_fast(1.0f + __expf(-x));
}
__device__ __forceinline__ float tanh_f(float x) {
  return 1.0f - 2.0f * rcp_fast(__expf(2.0f * x) + 1.0f);
}
__device__ __forceinline__ int load_len_(const void* sp, int b, int T, int p64) {
  int v = p64 ? (int)((const ll*)sp)[b] : ((const int*)sp)[b];
  return min(max(v, 1), T);
}
__device__ __forceinline__ int load_tok_(const void* st, ll idx, int t64) {
  return t64 ? (int)((const ll*)st)[idx] : ((const int*)st)[idx];
}

// ---------------- preamble 1: dtype detect + length histogram (1 CTA) -------
__global__ void k_prep(const int* tok, const int* pos, int B, int T) {
  __shared__ int h_sm[256];
  int i = threadIdx.x;
  if (i == 0) {
    int t64 = 1, p64 = 1;
#pragma unroll
    for (int k = 1; k < 32; k += 2) {
      if (tok[k] != 0) t64 = 0;
      if (pos[k] != 0) p64 = 0;
    }
    g_tok64 = t64;
    g_pos64 = p64;
  }
  h_sm[i] = 0;
  __syncthreads();
  int p64 = g_pos64;
  for (int b = i; b < B; b += 256) {
    int v = p64 ? (int)((const ll*)pos)[b] : pos[b];
    int len = min(max(v, 1), T);
    atomicAdd(&h_sm[min(T - len, 255)], 1);  // bin 0 = longest
  }
  __syncthreads();
  g_hist[i] = h_sm[i];
}

// ---------------- preamble 2: scan + scatter (1 CTA) ----------------
__global__ void k_scanscatter(const void* pos, int B, int T) {
  __shared__ int v[256];
  __shared__ int cur[256];
  int i = threadIdx.x;
  int x = g_hist[i];
  v[i] = x;
  __syncthreads();
#pragma unroll
  for (int off = 1; off < 256; off <<= 1) {
    int t = (i >= off) ? v[i - off] : 0;
    __syncthreads();
    v[i] += t;
    __syncthreads();
  }
  cur[i] = v[i] - x;
  __syncthreads();
  int p64 = g_pos64;
  for (int b = i; b < B; b += 256) {
    int len = load_len_(pos, b, T, p64);
    int bin = min(T - len, 255);
    int p = atomicAdd(&cur[bin], 1);
    if (p < MAXB) g_order[p] = b;
  }
}

// ---------------- vocab projection: g_proj = emb @ W_ih^T ----------------
// thread j owns W_ih row j in registers; CTA processes a contiguous vocab
// chunk, 16 rows per pipeline stage, double-buffered staging by all 192 thr.
#define PROJ_RPI 16
__global__ void __launch_bounds__(GDIM, 3) k_proj(const float* __restrict__ emb,
                                                  const float* __restrict__ W_ih,
                                                  int V) {
  __shared__ __align__(16) float e_sm[2][PROJ_RPI][HDIM];
  const int j = threadIdx.x;

  ull w[32];
  {
    const ulonglong2* wr = (const ulonglong2*)(W_ih + j * HDIM);
#pragma unroll
    for (int k = 0; k < 16; k++) {
      ulonglong2 a = wr[k];
      w[2 * k] = a.x;
      w[2 * k + 1] = a.y;
    }
  }

  int per = (V + gridDim.x - 1) / gridDim.x;
  per = (per + PROJ_RPI - 1) & ~(PROJ_RPI - 1);
  const int vbeg = blockIdx.x * per;
  const int vend = min(vbeg + per, V);
  if (vbeg >= vend) return;

  // stage first 16 rows into buf 0 (256 float4 by 192 threads)
  for (int i = j; i < PROJ_RPI * 16; i += GDIM) {
    int row = i >> 4, lane = i & 15;
    int v = vbeg + row;
    if (v < vend)
      ((float4*)e_sm[0][row])[lane] = ((const float4*)(emb + (ll)v * HDIM))[lane];
  }
  __syncthreads();

  int buf = 0;
  for (int v = vbeg; v < vend; v += PROJ_RPI) {
    for (int i = j; i < PROJ_RPI * 16; i += GDIM) {
      int row = i >> 4, lane = i & 15;
      int vn = v + PROJ_RPI + row;
      if (vn < vend)
        ((float4*)e_sm[buf ^ 1][row])[lane] =
            ((const float4*)(emb + (ll)vn * HDIM))[lane];
    }
    ull acc[PROJ_RPI];
#pragma unroll
    for (int i = 0; i < PROJ_RPI; i++) acc[i] = 0ull;
#pragma unroll
    for (int k = 0; k < 16; k++) {
#pragma unroll
      for (int i = 0; i < PROJ_RPI; i++) {
        ulonglong2 q = ((const ulonglong2*)e_sm[buf][i])[k];
        acc[i] = ffma2(w[2 * k], q.x, acc[i]);
        acc[i] = ffma2(w[2 * k + 1], q.y, acc[i]);
      }
    }
#pragma unroll
    for (int i = 0; i < PROJ_RPI; i++)
      if (v + i < vend) g_proj[(ll)(v + i) * GDIM + j] = pair_sum(acc[i]);
    __syncthreads();
    buf ^= 1;
  }
}

// ---------------- fused GRU recurrence (k-split) — R6 winner, reverted -----
// CTA = 128 threads. lane mapping: kh = (tid>>4)&1 (k-half), j = (tid&15) +
// 16*(tid>>5) (unit 0..63). Thread computes PARTIAL dots (its 32 k's) for all
// 4 rows x 3 gates (12 chains, W-half in 96 regs), combines with partner
// (lane^16, same warp) via shfl.xor, then finishes gates + h-update for its
// own 2 rows (kh=0 -> rows 0,1; kh=1 -> rows 2,3). One barrier per step.
// h stored per k-half with 36-float stride (bank-disjoint broadcast lines).
__global__ void __launch_bounds__(NTHR, 3) k_gru(
    const void* __restrict__ seq_token, const void* __restrict__ seq_pos,
    const float* __restrict__ W_hh, float* __restrict__ out, int B, int T) {
  __shared__ int tok_sm[ROWS][MAXT];
  __shared__ __align__(16) float h_sm[2][ROWS][2][36];  // [buf][row][khalf][32+pad]
  __shared__ int s_row[ROWS], s_len[ROWS];

  const int tid = threadIdx.x;
  const int kh = (tid >> 4) & 1;
  const int j = (tid & 15) | ((tid >> 5) << 4);
  const int rA = kh * 2, rB = rA + 1;  // own rows
  const int tok64 = g_tok64;

  if (tid < ROWS) {
    int idx = ROWS * blockIdx.x + tid;
    int row = (idx < B) ? g_order[idx] : -1;
    s_row[tid] = row;
    s_len[tid] = (row >= 0) ? load_len_(seq_pos, row, T, g_pos64) : 0;
  }
  __syncthreads();
  int tmax = max(max(s_len[0], s_len[1]), max(s_len[2], s_len[3]));
  if (tmax > MAXT) tmax = MAXT;
  const int lenA = s_len[rA], lenB = s_len[rB];

  // stage token ids (as int32) into smem
#pragma unroll
  for (int r = 0; r < ROWS; r++) {
    int rw = s_row[r];
    for (int i = tid; i < tmax; i += NTHR)
      tok_sm[r][i] = (rw >= 0) ? load_tok_(seq_token, (ll)rw * T + i, tok64) : 0;
  }

  // W_hh half-rows for unit j, 3 gates: 96 floats -> 48 ull regs
  ull wr[16], wz[16], wn[16];
  {
    const ulonglong2* p0 = (const ulonglong2*)(W_hh + j * HDIM + kh * 32);
    const ulonglong2* p1 = (const ulonglong2*)(W_hh + (HDIM + j) * HDIM + kh * 32);
    const ulonglong2* p2 = (const ulonglong2*)(W_hh + (2 * HDIM + j) * HDIM + kh * 32);
#pragma unroll
    for (int k = 0; k < 8; k++) {
      ulonglong2 a = p0[k];
      wr[2 * k] = a.x;
      wr[2 * k + 1] = a.y;
      ulonglong2 b = p1[k];
      wz[2 * k] = b.x;
      wz[2 * k + 1] = b.y;
      ulonglong2 c = p2[k];
      wn[2 * k] = c.x;
      wn[2 * k + 1] = c.y;
    }
  }

  // init h = 0 in buffer 0 (each thread inits its own-row slots)
  h_sm[0][rA][j >> 5][j & 31] = 0.0f;
  h_sm[0][rB][j >> 5][j & 31] = 0.0f;
  __syncthreads();  // tok_sm + h ready

  // gi for t=0 (own 2 rows x 3 gates)
  float grA, gzA, gnA, grB, gzB, gnB;
  {
    const float* pA = g_proj + (ll)tok_sm[rA][0] * GDIM + j;
    const float* pB = g_proj + (ll)tok_sm[rB][0] * GDIM + j;
    grA = pA[0]; gzA = pA[64]; gnA = pA[128];
    grB = pB[0]; gzB = pB[64]; gnB = pB[128];
  }

  for (int t = 0; t < tmax; t++) {
    const int cur = t & 1, nxt = cur ^ 1;

    // prefetch gi for t+1
    float qrA = 0.f, qzA = 0.f, qnA = 0.f, qrB = 0.f, qzB = 0.f, qnB = 0.f;
    if (t + 1 < tmax) {
      const float* pA = g_proj + (ll)tok_sm[rA][t + 1] * GDIM + j;
      const float* pB = g_proj + (ll)tok_sm[rB][t + 1] * GDIM + j;
      qrA = pA[0]; qzA = pA[64]; qnA = pA[128];
      qrB = pB[0]; qzB = pB[64]; qnB = pB[128];
    }

    // partial dots over this thread's k-half, all 4 rows x 3 gates
    ull acc[ROWS][3];
#pragma unroll
    for (int r = 0; r < ROWS; r++) {
      acc[r][0] = 0ull;
      acc[r][1] = 0ull;
      acc[r][2] = 0ull;
    }
#pragma unroll
    for (int k = 0; k < 8; k++) {
#pragma unroll
      for (int r = 0; r < ROWS; r++) {
        ulonglong2 hq = ((const ulonglong2*)h_sm[cur][r][kh])[k];
        acc[r][0] = ffma2(wr[2 * k], hq.x, acc[r][0]);
        acc[r][0] = ffma2(wr[2 * k + 1], hq.y, acc[r][0]);
        acc[r][1] = ffma2(wz[2 * k], hq.x, acc[r][1]);
        acc[r][1] = ffma2(wz[2 * k + 1], hq.y, acc[r][1]);
        acc[r][2] = ffma2(wn[2 * k], hq.x, acc[r][2]);
        acc[r][2] = ffma2(wn[2 * k + 1], hq.y, acc[r][2]);
      }
    }

    // combine halves with partner lane (lane ^ 16); all lanes execute all
    // 12 shfls; results consumed via kh-selects so none get DCE'd.
    float f[ROWS][3];
#pragma unroll
    for (int r = 0; r < ROWS; r++) {
#pragma unroll
      for (int gg = 0; gg < 3; gg++) {
        float p = pair_sum(acc[r][gg]);
        f[r][gg] = p + __shfl_xor_sync(0xffffffffu, p, 16);
      }
    }
    const float phrA = f[rA][0], phzA = f[rA][1], phnA = f[rA][2];
    const float phrB = f[rB][0], phzB = f[rB][1], phnB = f[rB][2];

    // gates + h update for own rows, fully in-thread
    {
      float rr = sigm(grA + phrA);
      float zz = sigm(gzA + phzA);
      float nn = tanh_f(gnA + rr * phnA);
      float ho = h_sm[cur][rA][j >> 5][j & 31];
      float hn = (1.0f - zz) * nn + zz * ho;
      h_sm[nxt][rA][j >> 5][j & 31] = (t < lenA) ? hn : ho;
    }
    {
      float rr = sigm(grB + phrB);
      float zz = sigm(gzB + phzB);
      float nn = tanh_f(gnB + rr * phnB);
      float ho = h_sm[cur][rB][j >> 5][j & 31];
      float hn = (1.0f - zz) * nn + zz * ho;
      h_sm[nxt][rB][j >> 5][j & 31] = (t < lenB) ? hn : ho;
    }
    __syncthreads();  // h[nxt] complete; fences reads of h[cur]

    grA = qrA; gzA = qzA; gnA = qnA;
    grB = qrB; gzB = qzB; gnB = qnB;
  }

  const int fb = tmax & 1;  // final h buffer
  {
    int row = s_row[rA];
    if (row >= 0) out[(ll)row * HDIM + j] = h_sm[fb][rA][j >> 5][j & 31];
    row = s_row[rB];
    if (row >= 0) out[(ll)row * HDIM + j] = h_sm[fb][rB][j >> 5][j & 31];
  }
}

// ---------------- launch ----------------
extern "C" void kernel_launch(void* const* d_in, const int* in_sizes, int n_in,
                              void* d_out, int out_size) {
  const void* tok = d_in[0];
  const void* pos = d_in[1];
  const float* emb = (const float*)d_in[2];
  const float* wih = (const float*)d_in[3];
  const float* whh = (const float*)d_in[4];
  float* out = (float*)d_out;

  const int B = in_sizes[1];
  const int T = in_sizes[0] / (B > 0 ? B : 1);
  int V = in_sizes[2] / HDIM;
  if (V > MAXV) V = MAXV;

  k_prep<<<1, 256>>>((const int*)tok, (const int*)pos, B, T);
  k_scanscatter<<<1, 256>>>(pos, B, T);
  k_proj<<<1184, GDIM>>>(emb, wih, V);

  const int nblk = (B + ROWS - 1) / ROWS;
  k_gru<<<nblk, NTHR>>>(tok, pos, whh, out, B, T);
}